// round 13
// baseline (speedup 1.0000x reference)
#include <cuda_runtime.h>
#include <cuda_fp16.h>
#include <cstdint>

// ============================================================================
// TensorTrain forward via mma.sync (single fp16 term) + fused rank contraction.
//   v3 = core3 @ X2                                   [32,4096]
//   GEMM pass0: perm(core2)@X1 tiles, epi * v3 -> u2  [32,4096]
//   GEMM pass1: perm(core1)@X0 tiles, epi * u2 -> u1  [32,4096]
//   Z = core0 @ u1                                    [512,4096]
//
// A (cores) pre-scaled x64, fp16; B (X) fp16. D = A*B (f32 accum), epi x 1/64.
// GEMM CTA tile: 128m x 256n, 512 threads (16 warps), grid (16 nq, 8 mt).
// BK=64 per pipeline stage (2 x 32-k sub-tiles), 2-stage cp.async, 8 mainloop
// iterations (halved barrier count vs BK=32).
//
// Packed GLOBAL layout per (tile, kc=32k) block of 2048 u32 words (dense):
//   word[row*16 + kp] = f16pair(M[row][2kp], M[row][2kp+1]),  kp in 0..15.
// SMEM sub-tile pads each 64 B row to 80 B: bankgroup(row,kg)=(5*row+kg)%8
//   -> 8 rows of every ldmatrix 8x8 tile hit 8 distinct groups (5 coprime 8).
// All pack/v3 work fused into ONE kernel (1D grid dispatch).
// __device__ globals are ONLY referenced from device code.
// ============================================================================

namespace {
constexpr int NB = 4096;
constexpr int D  = 512;
constexpr int R  = 32;
constexpr float ASCALE  = 64.f;
constexpr float UNSCALE = 1.f / 64.f;
constexpr int SM_ST    = 33280;             // sS: 32 x 260 f32
constexpr int TILE_B   = 10240;             // padded 32-k sub-tile (128 rows * 80)
constexpr int STAGE_B  = 6 * TILE_B;        // A(2) | B0(2) | B1(2) = 61440
constexpr int SM_TOTAL = SM_ST + 2 * STAGE_B;   // 156160
}

__device__ float g_V3[R * NB];
__device__ float g_u2[R * NB];
__device__ float g_u1[R * NB];
// A blocks: [mt(8)][kc(16)] x 2048 words ; B blocks: [nt(32)][kc(16)] x 2048 words
__device__ uint32_t g_A1[8 * 16 * 2048];
__device__ uint32_t g_A2[8 * 16 * 2048];
__device__ uint32_t g_B0[32 * 16 * 2048];
__device__ uint32_t g_B1[32 * 16 * 2048];

// ---------------------------------------------------------------------------
__device__ __forceinline__ uint32_t smem_u32(const void* p) {
    uint32_t a;
    asm("{ .reg .u64 t; cvta.to.shared.u64 t, %1; cvt.u32.u64 %0, t; }" : "=r"(a) : "l"(p));
    return a;
}
__device__ __forceinline__ void cp16(uint32_t saddr, const void* g) {
    asm volatile("cp.async.cg.shared.global [%0], [%1], 16;" :: "r"(saddr), "l"(g) : "memory");
}
#define CP_COMMIT() asm volatile("cp.async.commit_group;" ::: "memory")

__device__ __forceinline__ void mma16816(float* d, const uint32_t* a, const uint32_t* b) {
    asm volatile(
        "mma.sync.aligned.m16n8k16.row.col.f32.f16.f16.f32 "
        "{%0,%1,%2,%3}, {%4,%5,%6,%7}, {%8,%9}, {%0,%1,%2,%3};"
        : "+f"(d[0]), "+f"(d[1]), "+f"(d[2]), "+f"(d[3])
        : "r"(a[0]), "r"(a[1]), "r"(a[2]), "r"(a[3]), "r"(b[0]), "r"(b[1]));
}
__device__ __forceinline__ void ldsm4(uint32_t* r, uint32_t saddr) {
    asm volatile("ldmatrix.sync.aligned.m8n8.x4.shared.b16 {%0,%1,%2,%3}, [%4];"
                 : "=r"(r[0]), "=r"(r[1]), "=r"(r[2]), "=r"(r[3]) : "r"(saddr));
}
__device__ __forceinline__ uint32_t h2pack(__half a, __half b) {
    return ((uint32_t)__half_as_ushort(b) << 16) | __half_as_ushort(a);
}
__device__ __forceinline__ uint32_t pack_af(float x0, float x1) {
    return h2pack(__float2half_rn(x0 * ASCALE), __float2half_rn(x1 * ASCALE));
}
__device__ __forceinline__ uint32_t pack_bf(float x0, float x1) {
    return h2pack(__float2half_rn(x0), __float2half_rn(x1));
}

// ---------------------------------------------------------------------------
// Fused prep: pack cores, pack X, v3 in ONE launch. 1536 CTAs x 256 thr.
//   bid 0..255     : pack core  (mt = b&7, kc = (b>>3)&15, which = b>>7)
//   bid 256..1279  : pack X     (nt = r&31, kc = (r>>5)&15, which = r>>9)
//   bid 1280..1535 : v3 column group (n0 = (b-1280)*16)
// ---------------------------------------------------------------------------
__global__ __launch_bounds__(256)
void prep_kernel(const float* __restrict__ X0, const float* __restrict__ X1,
                 const float* __restrict__ X2, const float* __restrict__ c1,
                 const float* __restrict__ c2, const float* __restrict__ c3)
{
    __shared__ float sbuf[4 * 1056];   // 16896 B, reused by all branches
    const int bid = blockIdx.x, t = threadIdx.x;

    if (bid < 256) {
        // ---- pack core -> A blocks (dense) ----
        const float* __restrict__ core = ((bid >> 7) == 0) ? c1 : c2;
        uint32_t* __restrict__ out     = ((bid >> 7) == 0) ? g_A1 : g_A2;
        const int mt = bid & 7, kc = (bid >> 3) & 15;
#pragma unroll
        for (int i = 0; i < 16; i++) {
            int idx = t + i * 256;                 // 0..4095
            int a_loc = idx >> 10, rem = idx & 1023;
            int kloc = rem >> 5, b = rem & 31;
            sbuf[a_loc * 1056 + kloc * 33 + b] =
                core[(mt * 4 + a_loc) * (D * R) + kc * 1024 + rem];
        }
        __syncthreads();
        uint32_t* dst = out + (mt * 16 + kc) * 2048;
#pragma unroll
        for (int i = 0; i < 8; i++) {
            int w = t + i * 256;                   // 0..2047
            int m_loc = w >> 4, kp = w & 15;
            int a_loc = m_loc >> 5, b = m_loc & 31, k0 = kp * 2;
            float x0 = sbuf[a_loc * 1056 + k0 * 33 + b];
            float x1 = sbuf[a_loc * 1056 + (k0 + 1) * 33 + b];
            dst[w] = pack_af(x0, x1);
        }
    } else if (bid < 1280) {
        // ---- pack X -> B blocks (dense) ----
        const int r = bid - 256;
        const float* __restrict__ X = ((r >> 9) == 0) ? X0 : X1;
        uint32_t* __restrict__ out  = ((r >> 9) == 0) ? g_B0 : g_B1;
        const int nt = r & 31, kc = (r >> 5) & 15;
        float* sX = sbuf;                          // 32 x 129 = 4128 floats
#pragma unroll
        for (int i = 0; i < 16; i++) {
            int idx = t + i * 256;
            int k = idx >> 7, nl = idx & 127;
            sX[k * 129 + nl] = X[(kc * 32 + k) * NB + nt * 128 + nl];
        }
        __syncthreads();
        uint32_t* dst = out + (nt * 16 + kc) * 2048;
#pragma unroll
        for (int i = 0; i < 8; i++) {
            int w = t + i * 256;                   // 0..2047
            int n_loc = w >> 4, kp = w & 15;
            int k0 = kp * 2;
            dst[w] = pack_bf(sX[k0 * 129 + n_loc], sX[(k0 + 1) * 129 + n_loc]);
        }
    } else {
        // ---- v3[a,n] = sum_d core3[a,d] * X2[d,n], 16 cols per CTA ----
        const int n0 = (bid - 1280) * 16;
        float (*Xs)[17] = (float(*)[17])sbuf;      // 64 x 17 = 1088 floats
        const int a = t >> 3, ncp = (t & 7) * 2;
        float acc0 = 0.f, acc1 = 0.f;
        for (int d0 = 0; d0 < D; d0 += 64) {
#pragma unroll
            for (int i = 0; i < 4; i++) {
                int idx = t + i * 256;
                Xs[idx >> 4][idx & 15] = X2[(d0 + (idx >> 4)) * NB + n0 + (idx & 15)];
            }
            __syncthreads();
#pragma unroll
            for (int dl = 0; dl < 64; dl++) {
                float cv = c3[a * D + d0 + dl];
                acc0 += cv * Xs[dl][ncp];
                acc1 += cv * Xs[dl][ncp + 1];
            }
            __syncthreads();
        }
        g_V3[a * NB + n0 + ncp]     = acc0;
        g_V3[a * NB + n0 + ncp + 1] = acc1;
    }
}

// ---------------------------------------------------------------------------
// Tensor GEMM 128m x 256n, 512 threads / 16 warps, BK=64 2-stage pipeline.
// warps: wm = warp&3 (32 m rows = one 'a'), wn = warp>>2 (64-col n slice).
// grid (nq=16, mt=8) = 128 CTAs.
// pass 0: A=g_A2, B=g_B1, scale=g_V3, out=g_u2
// pass 1: A=g_A1, B=g_B0, scale=g_u2, out=g_u1
// out[a, n] = (1/64) * sum_b C[a*32+b, n] * scale[b, n],  a = mt*4 + wm.
// ---------------------------------------------------------------------------
__global__ __launch_bounds__(512, 1)
void tt_gemm_kernel(int pass)
{
    const uint32_t* __restrict__ Apk   = (pass == 0) ? g_A2 : g_A1;
    const uint32_t* __restrict__ Bpk   = (pass == 0) ? g_B1 : g_B0;
    const float*    __restrict__ scale = (pass == 0) ? g_V3 : g_u2;
    float*          __restrict__ out   = (pass == 0) ? g_u2 : g_u1;

    extern __shared__ char smem[];
    const int t = threadIdx.x, warp = t >> 5, lane = t & 31;
    const int wm = warp & 3, wn = warp >> 2;        // wn 0..3: 64-col slice
    const int g = lane >> 2, c = lane & 3;
    const int nq = blockIdx.x, mt = blockIdx.y;
    const uint32_t sbase = smem_u32(smem);

    // ldmatrix per-lane row geometry (loop-invariant)
    const int mat  = lane >> 3;          // 0..3
    const int mrow = lane & 7;
    const int hA = mat >> 1;                                     // A k-half
    const int rA0 = (wm * 2 + 0) * 16 + (mat & 1) * 8 + mrow;    // i=0 row
    const int rA1 = rA0 + 16;                                    // i=1 row
    const int hB = mat & 1;                                      // B k-half
    const int rB = (wn & 1) * 64 + (mat >> 1) * 8 + mrow;        // + jp*8

    // scale tile: 32 x 256, stride 260
    float* sS = (float*)smem;
#pragma unroll
    for (int i = 0; i < 16; i++) {
        int idx = t + i * 512;
        sS[(idx >> 8) * 260 + (idx & 255)] = scale[(idx >> 8) * NB + nq * 256 + (idx & 255)];
    }

    const uint32_t* Asrc  = Apk + mt * 32768;             // 16 kc * 2048
    const uint32_t* B0src = Bpk + (nq * 2 + 0) * 32768;
    const uint32_t* B1src = Bpk + (nq * 2 + 1) * 32768;

    float acc[2][8][4];
#pragma unroll
    for (int i = 0; i < 2; i++)
#pragma unroll
        for (int j = 0; j < 8; j++)
#pragma unroll
            for (int q = 0; q < 4; q++) acc[i][j][q] = 0.f;

    // padded smem offset for chunk j in a 32-k sub-tile: j*16 + (j>>2)*16
    const uint32_t o1 = (uint32_t)t * 16 + (uint32_t)(t & ~3) * 4;

    // issue one BK=64 stage (2 sub-tiles per operand, 6 cp16/thread)
    auto issue = [&](int kq) {
        uint32_t sd = sbase + SM_ST + (kq & 1) * STAGE_B;
        const uint4* a4  = (const uint4*)(Asrc  + kq * 4096);
        const uint4* b04 = (const uint4*)(B0src + kq * 4096);
        const uint4* b14 = (const uint4*)(B1src + kq * 4096);
        cp16(sd + o1,              a4 + t);
        cp16(sd + TILE_B + o1,     a4 + t + 512);
        cp16(sd + 2 * TILE_B + o1, b04 + t);
        cp16(sd + 3 * TILE_B + o1, b04 + t + 512);
        cp16(sd + 4 * TILE_B + o1, b14 + t);
        cp16(sd + 5 * TILE_B + o1, b14 + t + 512);
        CP_COMMIT();
    };
    issue(0);

    for (int kq = 0; kq < 8; kq++) {
        asm volatile("cp.async.wait_group 0;" ::: "memory");
        __syncthreads();                       // stage kq visible to all
        if (kq + 1 < 8) issue(kq + 1);         // fills other stage (consumed @ kq-1)

        const uint32_t stg = sbase + SM_ST + (kq & 1) * STAGE_B;

#pragma unroll
        for (int sub = 0; sub < 2; sub++) {
            const uint32_t sA = stg + (uint32_t)sub * TILE_B;
            const uint32_t sB = stg + 2 * TILE_B + (uint32_t)(wn >> 1) * (2 * TILE_B)
                                + (uint32_t)sub * TILE_B;
#pragma unroll
            for (int ks = 0; ks < 2; ks++) {
                uint32_t ah[2][4];
                {
                    uint32_t kgA = (uint32_t)(ks * 2 + hA);
                    ldsm4(ah[0], sA + (uint32_t)rA0 * 80 + kgA * 16);
                    ldsm4(ah[1], sA + (uint32_t)rA1 * 80 + kgA * 16);
                }
#pragma unroll
                for (int jp = 0; jp < 8; jp += 2) {
                    uint32_t bb[4];
                    {
                        int rn = rB + jp * 8;
                        uint32_t kgB = (uint32_t)(ks * 2 + hB);
                        ldsm4(bb, sB + (uint32_t)rn * 80 + kgB * 16);
                    }
#pragma unroll
                    for (int i = 0; i < 2; i++) {
                        mma16816(acc[i][jp],     ah[i], bb);
                        mma16816(acc[i][jp + 1], ah[i], bb + 2);
                    }
                }
            }
        }
    }

    // epilogue: contract over b = rows of the warp's 32-row strip, unscale
    const int a = mt * 4 + wm;
    float* dst = out + a * NB + nq * 256 + wn * 64;
#pragma unroll
    for (int j = 0; j < 8; j++) {
        int col0 = wn * 64 + j * 8 + c * 2;
        float p0 = 0.f, p1 = 0.f;
#pragma unroll
        for (int i = 0; i < 2; i++) {
            int b0 = i * 16 + g, b1 = b0 + 8;
            p0 += acc[i][j][0] * sS[b0 * 260 + col0] + acc[i][j][2] * sS[b1 * 260 + col0];
            p1 += acc[i][j][1] * sS[b0 * 260 + col0 + 1] + acc[i][j][3] * sS[b1 * 260 + col0 + 1];
        }
#pragma unroll
        for (int off = 4; off <= 16; off <<= 1) {
            p0 += __shfl_xor_sync(0xffffffffu, p0, off);
            p1 += __shfl_xor_sync(0xffffffffu, p1, off);
        }
        if (g == 0)
            *(float2*)&dst[j * 8 + c * 2] = make_float2(p0 * UNSCALE, p1 * UNSCALE);
    }
}

// ---------------------------------------------------------------------------
// Z[o,n] = sum_a core0[o*32+a] * u1[a,n]   (reads g_u1 directly)
// ---------------------------------------------------------------------------
__global__ __launch_bounds__(256)
void z_kernel(const float* __restrict__ core0, float* __restrict__ Z)
{
    __shared__ float cs[64 * 32];
    __shared__ float u1s[32][133];
    const int t = threadIdx.x, nt = blockIdx.x, og = blockIdx.y;
    const int n0 = nt * 128;
#pragma unroll
    for (int i = 0; i < 8; i++)
        cs[i * 256 + t] = core0[og * 64 * 32 + i * 256 + t];
#pragma unroll
    for (int i = 0; i < 16; i++) {
        int idx = t + i * 256;
        u1s[idx >> 7][idx & 127] = g_u1[(idx >> 7) * NB + n0 + (idx & 127)];
    }
    __syncthreads();
    const int j = t & 127, to = t >> 7;
    float u1r[32];
#pragma unroll
    for (int a = 0; a < 32; a++) u1r[a] = u1s[a][j];
#pragma unroll 4
    for (int oo = 0; oo < 32; oo++) {
        int ol = to * 32 + oo;
        float acc = 0.f;
#pragma unroll
        for (int a = 0; a < 32; a++)
            acc += cs[ol * 32 + a] * u1r[a];
        Z[(og * 64 + ol) * NB + n0 + j] = acc;
    }
}

// ---------------------------------------------------------------------------
extern "C" void kernel_launch(void* const* d_in, const int* in_sizes, int n_in,
                              void* d_out, int out_size)
{
    const float* X0    = (const float*)d_in[0];
    const float* X1    = (const float*)d_in[1];
    const float* X2    = (const float*)d_in[2];
    const float* core0 = (const float*)d_in[3];
    const float* core1 = (const float*)d_in[4];
    const float* core2 = (const float*)d_in[5];
    const float* core3 = (const float*)d_in[6];
    float* Z = (float*)d_out;

    static bool attr_done = false;
    if (!attr_done) {
        cudaFuncSetAttribute(tt_gemm_kernel,
                             cudaFuncAttributeMaxDynamicSharedMemorySize, SM_TOTAL);
        attr_done = true;
    }

    prep_kernel<<<1536, 256>>>(X0, X1, X2, core1, core2, core3);
    tt_gemm_kernel<<<dim3(16, 8), 512, SM_TOTAL>>>(0);  // core2 x X1, scale v3 -> u2
    tt_gemm_kernel<<<dim3(16, 8), 512, SM_TOTAL>>>(1);  // core1 x X0, scale u2 -> u1
    z_kernel<<<dim3(32, 8), 256>>>(core0, Z);
}

// round 14
// speedup vs baseline: 1.0780x; 1.0780x over previous
#include <cuda_runtime.h>
#include <cuda_fp16.h>
#include <cstdint>

// ============================================================================
// TensorTrain forward via mma.sync (single fp16 term) + fused rank contraction.
//   v3 = core3 @ X2                                   [32,4096]
//   GEMM pass0: perm(core2)@X1 tiles, epi * v3 -> u2  [32,4096]
//   GEMM pass1: perm(core1)@X0 tiles, epi * u2 -> u1  [32,4096]
//   Z = core0 @ u1                                    [512,4096]
//
// A (cores) pre-scaled x64, fp16; B (X) fp16. D = A*B (f32 accum), epi x 1/64.
// GEMM CTA tile: 128m x 256n, 512 threads (16 warps), grid (16 nq, 8 mt),
// BK=32, 3-stage cp.async pipeline (the measured-best R12 configuration).
//
// Packed GLOBAL layout per (tile, kc=32k) block of 2048 u32 words (dense):
//   word[row*16 + kp] = f16pair(M[row][2kp], M[row][2kp+1]),  kp in 0..15.
// SMEM stage pads each 64 B row to 80 B: bankgroup(row,kg)=(5*row+kg)%8
//   -> 8 rows of every ldmatrix 8x8 tile hit 8 distinct groups (5 coprime 8).
// Prep (v3 + both packs) fused into ONE kernel, v3 CTAs FIRST (longest work
// scheduled in wave 1; light pack CTAs backfill -> no tail).
// __device__ globals are ONLY referenced from device code.
// ============================================================================

namespace {
constexpr int NB = 4096;
constexpr int D  = 512;
constexpr int R  = 32;
constexpr float ASCALE  = 64.f;
constexpr float UNSCALE = 1.f / 64.f;
constexpr int SM_ST    = 33280;             // sS: 32 x 260 f32
constexpr int TILE_B   = 10240;             // padded tile bytes (128 rows * 80)
constexpr int STAGE_B  = 3 * TILE_B;        // 30720
constexpr int SM_TOTAL = SM_ST + 3 * STAGE_B;   // 125440
}

__device__ float g_V3[R * NB];
__device__ float g_u2[R * NB];
__device__ float g_u1[R * NB];
// A blocks: [mt(8)][kc(16)] x 2048 words ; B blocks: [nt(32)][kc(16)] x 2048 words
__device__ uint32_t g_A1[8 * 16 * 2048];
__device__ uint32_t g_A2[8 * 16 * 2048];
__device__ uint32_t g_B0[32 * 16 * 2048];
__device__ uint32_t g_B1[32 * 16 * 2048];

// ---------------------------------------------------------------------------
__device__ __forceinline__ uint32_t smem_u32(const void* p) {
    uint32_t a;
    asm("{ .reg .u64 t; cvta.to.shared.u64 t, %1; cvt.u32.u64 %0, t; }" : "=r"(a) : "l"(p));
    return a;
}
__device__ __forceinline__ void cp16(uint32_t saddr, const void* g) {
    asm volatile("cp.async.cg.shared.global [%0], [%1], 16;" :: "r"(saddr), "l"(g) : "memory");
}
#define CP_COMMIT() asm volatile("cp.async.commit_group;" ::: "memory")

__device__ __forceinline__ void mma16816(float* d, const uint32_t* a, const uint32_t* b) {
    asm volatile(
        "mma.sync.aligned.m16n8k16.row.col.f32.f16.f16.f32 "
        "{%0,%1,%2,%3}, {%4,%5,%6,%7}, {%8,%9}, {%0,%1,%2,%3};"
        : "+f"(d[0]), "+f"(d[1]), "+f"(d[2]), "+f"(d[3])
        : "r"(a[0]), "r"(a[1]), "r"(a[2]), "r"(a[3]), "r"(b[0]), "r"(b[1]));
}
__device__ __forceinline__ void ldsm4(uint32_t* r, uint32_t saddr) {
    asm volatile("ldmatrix.sync.aligned.m8n8.x4.shared.b16 {%0,%1,%2,%3}, [%4];"
                 : "=r"(r[0]), "=r"(r[1]), "=r"(r[2]), "=r"(r[3]) : "r"(saddr));
}
__device__ __forceinline__ uint32_t h2pack(__half a, __half b) {
    return ((uint32_t)__half_as_ushort(b) << 16) | __half_as_ushort(a);
}
__device__ __forceinline__ uint32_t pack_af(float x0, float x1) {
    return h2pack(__float2half_rn(x0 * ASCALE), __float2half_rn(x1 * ASCALE));
}
__device__ __forceinline__ uint32_t pack_bf(float x0, float x1) {
    return h2pack(__float2half_rn(x0), __float2half_rn(x1));
}

// ---------------------------------------------------------------------------
// Fused prep: v3 FIRST, then pack cores, then pack X. 1536 CTAs x 256 thr.
//   bid 0..255     : v3 column group (n0 = bid*16)
//   bid 256..511   : pack core (r=bid-256: mt=r&7, kc=(r>>3)&15, which=r>>7)
//   bid 512..1535  : pack X    (r=bid-512: nt=r&31, kc=(r>>5)&15, which=r>>9)
// ---------------------------------------------------------------------------
__global__ __launch_bounds__(256)
void prep_kernel(const float* __restrict__ X0, const float* __restrict__ X1,
                 const float* __restrict__ X2, const float* __restrict__ c1,
                 const float* __restrict__ c2, const float* __restrict__ c3)
{
    __shared__ float sbuf[4 * 1056];   // 16896 B, reused by all branches
    const int bid = blockIdx.x, t = threadIdx.x;

    if (bid < 256) {
        // ---- v3[a,n] = sum_d core3[a,d] * X2[d,n], 16 cols per CTA ----
        const int n0 = bid * 16;
        float (*Xs)[17] = (float(*)[17])sbuf;      // 64 x 17
        const int a = t >> 3, ncp = (t & 7) * 2;
        float acc0 = 0.f, acc1 = 0.f;
        for (int d0 = 0; d0 < D; d0 += 64) {
#pragma unroll
            for (int i = 0; i < 4; i++) {
                int idx = t + i * 256;
                Xs[idx >> 4][idx & 15] = X2[(d0 + (idx >> 4)) * NB + n0 + (idx & 15)];
            }
            __syncthreads();
#pragma unroll
            for (int dl = 0; dl < 64; dl++) {
                float cv = c3[a * D + d0 + dl];
                acc0 += cv * Xs[dl][ncp];
                acc1 += cv * Xs[dl][ncp + 1];
            }
            __syncthreads();
        }
        g_V3[a * NB + n0 + ncp]     = acc0;
        g_V3[a * NB + n0 + ncp + 1] = acc1;
    } else if (bid < 512) {
        // ---- pack core -> A blocks (dense) ----
        const int r = bid - 256;
        const float* __restrict__ core = ((r >> 7) == 0) ? c1 : c2;
        uint32_t* __restrict__ out     = ((r >> 7) == 0) ? g_A1 : g_A2;
        const int mt = r & 7, kc = (r >> 3) & 15;
#pragma unroll
        for (int i = 0; i < 16; i++) {
            int idx = t + i * 256;                 // 0..4095
            int a_loc = idx >> 10, rem = idx & 1023;
            int kloc = rem >> 5, b = rem & 31;
            sbuf[a_loc * 1056 + kloc * 33 + b] =
                core[(mt * 4 + a_loc) * (D * R) + kc * 1024 + rem];
        }
        __syncthreads();
        uint32_t* dst = out + (mt * 16 + kc) * 2048;
#pragma unroll
        for (int i = 0; i < 8; i++) {
            int w = t + i * 256;                   // 0..2047
            int m_loc = w >> 4, kp = w & 15;
            int a_loc = m_loc >> 5, b = m_loc & 31, k0 = kp * 2;
            float x0 = sbuf[a_loc * 1056 + k0 * 33 + b];
            float x1 = sbuf[a_loc * 1056 + (k0 + 1) * 33 + b];
            dst[w] = pack_af(x0, x1);
        }
    } else {
        // ---- pack X -> B blocks (dense) ----
        const int r = bid - 512;
        const float* __restrict__ X = ((r >> 9) == 0) ? X0 : X1;
        uint32_t* __restrict__ out  = ((r >> 9) == 0) ? g_B0 : g_B1;
        const int nt = r & 31, kc = (r >> 5) & 15;
        float* sX = sbuf;                          // 32 x 129
#pragma unroll
        for (int i = 0; i < 16; i++) {
            int idx = t + i * 256;
            int k = idx >> 7, nl = idx & 127;
            sX[k * 129 + nl] = X[(kc * 32 + k) * NB + nt * 128 + nl];
        }
        __syncthreads();
        uint32_t* dst = out + (nt * 16 + kc) * 2048;
#pragma unroll
        for (int i = 0; i < 8; i++) {
            int w = t + i * 256;                   // 0..2047
            int n_loc = w >> 4, kp = w & 15;
            int k0 = kp * 2;
            dst[w] = pack_bf(sX[k0 * 129 + n_loc], sX[(k0 + 1) * 129 + n_loc]);
        }
    }
}

// ---------------------------------------------------------------------------
// Tensor GEMM 128m x 256n, 512 threads / 16 warps (4 per SMSP).  [R12 verbatim]
// warps: wm = warp&3 (32 m rows = one 'a'), wn = warp>>2 (64-col n slice).
// grid (nq=16, mt=8) = 128 CTAs. BK=32, 3-stage cp.async, 80B-padded rows.
// pass 0: A=g_A2, B=g_B1, scale=g_V3, out=g_u2
// pass 1: A=g_A1, B=g_B0, scale=g_u2, out=g_u1
// out[a, n] = (1/64) * sum_b C[a*32+b, n] * scale[b, n],  a = mt*4 + wm.
// ---------------------------------------------------------------------------
__global__ __launch_bounds__(512, 1)
void tt_gemm_kernel(int pass)
{
    const uint32_t* __restrict__ Apk   = (pass == 0) ? g_A2 : g_A1;
    const uint32_t* __restrict__ Bpk   = (pass == 0) ? g_B1 : g_B0;
    const float*    __restrict__ scale = (pass == 0) ? g_V3 : g_u2;
    float*          __restrict__ out   = (pass == 0) ? g_u2 : g_u1;

    extern __shared__ char smem[];
    const int t = threadIdx.x, warp = t >> 5, lane = t & 31;
    const int wm = warp & 3, wn = warp >> 2;        // wn 0..3: 64-col slice
    const int g = lane >> 2, c = lane & 3;
    const int nq = blockIdx.x, mt = blockIdx.y;
    const uint32_t sbase = smem_u32(smem);

    const int mat  = lane >> 3;          // 0..3
    const int mrow = lane & 7;
    const int hA = mat >> 1;                                     // A k-half
    const int rA0 = (wm * 2 + 0) * 16 + (mat & 1) * 8 + mrow;    // i=0 row
    const int rA1 = rA0 + 16;                                    // i=1 row
    const int hB = mat & 1;                                      // B k-half
    const int rB = (wn & 1) * 64 + (mat >> 1) * 8 + mrow;        // + jp*8

    // scale tile: 32 x 256, stride 260
    float* sS = (float*)smem;
#pragma unroll
    for (int i = 0; i < 16; i++) {
        int idx = t + i * 512;
        sS[(idx >> 8) * 260 + (idx & 255)] = scale[(idx >> 8) * NB + nq * 256 + (idx & 255)];
    }

    const uint32_t* Asrc  = Apk + mt * 32768;             // 16 kc * 2048
    const uint32_t* B0src = Bpk + (nq * 2 + 0) * 32768;
    const uint32_t* B1src = Bpk + (nq * 2 + 1) * 32768;

    float acc[2][8][4];
#pragma unroll
    for (int i = 0; i < 2; i++)
#pragma unroll
        for (int j = 0; j < 8; j++)
#pragma unroll
            for (int q = 0; q < 4; q++) acc[i][j][q] = 0.f;

    // padded smem offset for this thread's 16B chunk
    const uint32_t o1 = (uint32_t)t * 16 + (uint32_t)(t & ~3) * 4;

    auto issue = [&](int kc) {
        uint32_t sd = sbase + SM_ST + (kc % 3) * STAGE_B;
        cp16(sd + o1,              (const uint4*)(Asrc  + kc * 2048) + t);
        cp16(sd + TILE_B + o1,     (const uint4*)(B0src + kc * 2048) + t);
        cp16(sd + 2 * TILE_B + o1, (const uint4*)(B1src + kc * 2048) + t);
        CP_COMMIT();
    };
    issue(0);
    issue(1);

    for (int kc = 0; kc < 16; kc++) {
        if (kc < 15)
            asm volatile("cp.async.wait_group 1;" ::: "memory");
        else
            asm volatile("cp.async.wait_group 0;" ::: "memory");
        __syncthreads();                       // stage kc visible to all
        if (kc + 2 < 16) issue(kc + 2);        // overwrites stage (kc-1)%3: safe

        const uint32_t sA = sbase + SM_ST + (kc % 3) * STAGE_B;
        const uint32_t sB = sA + TILE_B + (uint32_t)(wn >> 1) * TILE_B;

#pragma unroll
        for (int ks = 0; ks < 2; ks++) {
            uint32_t ah[2][4];
            {
                uint32_t kgA = (uint32_t)(ks * 2 + hA);
                ldsm4(ah[0], sA + (uint32_t)rA0 * 80 + kgA * 16);
                ldsm4(ah[1], sA + (uint32_t)rA1 * 80 + kgA * 16);
            }
#pragma unroll
            for (int jp = 0; jp < 8; jp += 2) {
                uint32_t bb[4];
                {
                    int rn = rB + jp * 8;
                    uint32_t kgB = (uint32_t)(ks * 2 + hB);
                    ldsm4(bb, sB + (uint32_t)rn * 80 + kgB * 16);
                }
#pragma unroll
                for (int i = 0; i < 2; i++) {
                    mma16816(acc[i][jp],     ah[i], bb);
                    mma16816(acc[i][jp + 1], ah[i], bb + 2);
                }
            }
        }
    }

    // epilogue: contract over b = rows of the warp's 32-row strip, unscale
    const int a = mt * 4 + wm;
    float* dst = out + a * NB + nq * 256 + wn * 64;
#pragma unroll
    for (int j = 0; j < 8; j++) {
        int col0 = wn * 64 + j * 8 + c * 2;
        float p0 = 0.f, p1 = 0.f;
#pragma unroll
        for (int i = 0; i < 2; i++) {
            int b0 = i * 16 + g, b1 = b0 + 8;
            p0 += acc[i][j][0] * sS[b0 * 260 + col0] + acc[i][j][2] * sS[b1 * 260 + col0];
            p1 += acc[i][j][1] * sS[b0 * 260 + col0 + 1] + acc[i][j][3] * sS[b1 * 260 + col0 + 1];
        }
#pragma unroll
        for (int off = 4; off <= 16; off <<= 1) {
            p0 += __shfl_xor_sync(0xffffffffu, p0, off);
            p1 += __shfl_xor_sync(0xffffffffu, p1, off);
        }
        if (g == 0)
            *(float2*)&dst[j * 8 + c * 2] = make_float2(p0 * UNSCALE, p1 * UNSCALE);
    }
}

// ---------------------------------------------------------------------------
// Z[o,n] = sum_a core0[o*32+a] * u1[a,n].  grid (32 nt, 16 og) = 512 CTAs,
// 256 thr; each CTA 32 o x 128 n, each thread 16 outputs (occ 2x vs before).
// ---------------------------------------------------------------------------
__global__ __launch_bounds__(256)
void z_kernel(const float* __restrict__ core0, float* __restrict__ Z)
{
    __shared__ float cs[32 * 32];
    __shared__ float u1s[32][133];
    const int t = threadIdx.x, nt = blockIdx.x, og = blockIdx.y;
    const int n0 = nt * 128;
#pragma unroll
    for (int i = 0; i < 4; i++)
        cs[i * 256 + t] = core0[og * 32 * 32 + i * 256 + t];
#pragma unroll
    for (int i = 0; i < 16; i++) {
        int idx = t + i * 256;
        u1s[idx >> 7][idx & 127] = g_u1[(idx >> 7) * NB + n0 + (idx & 127)];
    }
    __syncthreads();
    const int j = t & 127, to = t >> 7;            // to: 0..1 -> 16 o each
    float u1r[32];
#pragma unroll
    for (int a = 0; a < 32; a++) u1r[a] = u1s[a][j];
#pragma unroll
    for (int oo = 0; oo < 16; oo++) {
        int ol = to * 16 + oo;
        float acc = 0.f;
#pragma unroll
        for (int a = 0; a < 32; a++)
            acc += cs[ol * 32 + a] * u1r[a];
        Z[(og * 32 + ol) * NB + n0 + j] = acc;
    }
}

// ---------------------------------------------------------------------------
extern "C" void kernel_launch(void* const* d_in, const int* in_sizes, int n_in,
                              void* d_out, int out_size)
{
    const float* X0    = (const float*)d_in[0];
    const float* X1    = (const float*)d_in[1];
    const float* X2    = (const float*)d_in[2];
    const float* core0 = (const float*)d_in[3];
    const float* core1 = (const float*)d_in[4];
    const float* core2 = (const float*)d_in[5];
    const float* core3 = (const float*)d_in[6];
    float* Z = (float*)d_out;

    static bool attr_done = false;
    if (!attr_done) {
        cudaFuncSetAttribute(tt_gemm_kernel,
                             cudaFuncAttributeMaxDynamicSharedMemorySize, SM_TOTAL);
        attr_done = true;
    }

    prep_kernel<<<1536, 256>>>(X0, X1, X2, core1, core2, core3);
    tt_gemm_kernel<<<dim3(16, 8), 512, SM_TOTAL>>>(0);  // core2 x X1, scale v3 -> u2
    tt_gemm_kernel<<<dim3(16, 8), 512, SM_TOTAL>>>(1);  // core1 x X0, scale u2 -> u1
    z_kernel<<<dim3(32, 16), 256>>>(core0, Z);
}

// round 15
// speedup vs baseline: 1.1761x; 1.0909x over previous
#include <cuda_runtime.h>
#include <cuda_fp16.h>
#include <cstdint>

// ============================================================================
// TensorTrain forward via mma.sync (single fp16 term) + fused rank contraction.
//   v3 = core3 @ X2                                   [32,4096]
//   GEMM pass0: perm(core2)@X1 tiles, epi * v3 -> u2  [32,4096]
//   GEMM pass1: perm(core1)@X0 tiles, epi * u2 -> u1  [32,4096]
//   Z = core0 @ u1                                    [512,4096]
//
// A (cores) pre-scaled x64, fp16; B (X) fp16. D = A*B (f32 accum), epi x 1/64.
// GEMM CTA tile: 128m x 256n, 512 threads (16 warps), grid (16 nq, 8 mt),
// BK=32, 3-stage cp.async (measured-best R12 configuration, restored verbatim).
// z_kernel: float4 cs loads (4x fewer LDS) + paired-output ILP.
//
// Packed GLOBAL layout per (tile, kc=32k) block of 2048 u32 words (dense):
//   word[row*16 + kp] = f16pair(M[row][2kp], M[row][2kp+1]),  kp in 0..15.
// SMEM stage pads each 64 B row to 80 B: bankgroup(row,kg)=(5*row+kg)%8
//   -> 8 rows of every ldmatrix 8x8 tile hit 8 distinct groups (5 coprime 8).
// __device__ globals are ONLY referenced from device code (selected by flag).
// ============================================================================

namespace {
constexpr int NB = 4096;
constexpr int D  = 512;
constexpr int R  = 32;
constexpr float ASCALE  = 64.f;
constexpr float UNSCALE = 1.f / 64.f;
constexpr int SM_ST    = 33280;             // sS: 32 x 260 f32
constexpr int TILE_B   = 10240;             // padded tile bytes (128 rows * 80)
constexpr int STAGE_B  = 3 * TILE_B;        // 30720
constexpr int SM_TOTAL = SM_ST + 3 * STAGE_B;   // 125440
}

__device__ float g_V3[R * NB];
__device__ float g_u2[R * NB];
__device__ float g_u1[R * NB];
// A blocks: [mt(8)][kc(16)] x 2048 words ; B blocks: [nt(32)][kc(16)] x 2048 words
__device__ uint32_t g_A1[8 * 16 * 2048];
__device__ uint32_t g_A2[8 * 16 * 2048];
__device__ uint32_t g_B0[32 * 16 * 2048];
__device__ uint32_t g_B1[32 * 16 * 2048];

// ---------------------------------------------------------------------------
__device__ __forceinline__ uint32_t smem_u32(const void* p) {
    uint32_t a;
    asm("{ .reg .u64 t; cvta.to.shared.u64 t, %1; cvt.u32.u64 %0, t; }" : "=r"(a) : "l"(p));
    return a;
}
__device__ __forceinline__ void cp16(uint32_t saddr, const void* g) {
    asm volatile("cp.async.cg.shared.global [%0], [%1], 16;" :: "r"(saddr), "l"(g) : "memory");
}
#define CP_COMMIT() asm volatile("cp.async.commit_group;" ::: "memory")

__device__ __forceinline__ void mma16816(float* d, const uint32_t* a, const uint32_t* b) {
    asm volatile(
        "mma.sync.aligned.m16n8k16.row.col.f32.f16.f16.f32 "
        "{%0,%1,%2,%3}, {%4,%5,%6,%7}, {%8,%9}, {%0,%1,%2,%3};"
        : "+f"(d[0]), "+f"(d[1]), "+f"(d[2]), "+f"(d[3])
        : "r"(a[0]), "r"(a[1]), "r"(a[2]), "r"(a[3]), "r"(b[0]), "r"(b[1]));
}
__device__ __forceinline__ void ldsm4(uint32_t* r, uint32_t saddr) {
    asm volatile("ldmatrix.sync.aligned.m8n8.x4.shared.b16 {%0,%1,%2,%3}, [%4];"
                 : "=r"(r[0]), "=r"(r[1]), "=r"(r[2]), "=r"(r[3]) : "r"(saddr));
}
__device__ __forceinline__ uint32_t h2pack(__half a, __half b) {
    return ((uint32_t)__half_as_ushort(b) << 16) | __half_as_ushort(a);
}
__device__ __forceinline__ uint32_t pack_af(float x0, float x1) {
    return h2pack(__float2half_rn(x0 * ASCALE), __float2half_rn(x1 * ASCALE));
}
__device__ __forceinline__ uint32_t pack_bf(float x0, float x1) {
    return h2pack(__float2half_rn(x0), __float2half_rn(x1));
}

// ---------------------------------------------------------------------------
// Pack both cores -> A blocks (dense). grid (mt=8, kc=16, z=2), 256 thr.
// ---------------------------------------------------------------------------
__global__ __launch_bounds__(256)
void pack_core_kernel(const float* __restrict__ c1, const float* __restrict__ c2)
{
    const float* __restrict__ core = (blockIdx.z == 0) ? c1 : c2;
    uint32_t* __restrict__ out     = (blockIdx.z == 0) ? g_A1 : g_A2;
    __shared__ float sC[4 * 1056];    // [a_loc][kloc(32) stride 33][b(32)]
    const int t = threadIdx.x, mt = blockIdx.x, kc = blockIdx.y;
#pragma unroll
    for (int i = 0; i < 16; i++) {
        int idx = t + i * 256;                 // 0..4095
        int a_loc = idx >> 10, rem = idx & 1023;
        int kloc = rem >> 5, b = rem & 31;
        sC[a_loc * 1056 + kloc * 33 + b] =
            core[(mt * 4 + a_loc) * (D * R) + kc * 1024 + rem];
    }
    __syncthreads();
    uint32_t* dst = out + (mt * 16 + kc) * 2048;
#pragma unroll
    for (int i = 0; i < 8; i++) {
        int w = t + i * 256;                   // 0..2047
        int m_loc = w >> 4, kp = w & 15;
        int a_loc = m_loc >> 5, b = m_loc & 31, k0 = kp * 2;
        float x0 = sC[a_loc * 1056 + k0 * 33 + b];
        float x1 = sC[a_loc * 1056 + (k0 + 1) * 33 + b];
        dst[w] = pack_af(x0, x1);
    }
}

// ---------------------------------------------------------------------------
// Pack both X -> B blocks (dense). grid (nt=32, kc=16, z=2), 256 thr.
// ---------------------------------------------------------------------------
__global__ __launch_bounds__(256)
void pack_x_kernel(const float* __restrict__ x0p, const float* __restrict__ x1p)
{
    const float* __restrict__ X = (blockIdx.z == 0) ? x0p : x1p;
    uint32_t* __restrict__ out  = (blockIdx.z == 0) ? g_B0 : g_B1;
    __shared__ float sX[32 * 129];
    const int t = threadIdx.x, nt = blockIdx.x, kc = blockIdx.y;
#pragma unroll
    for (int i = 0; i < 16; i++) {
        int idx = t + i * 256;
        int k = idx >> 7, nl = idx & 127;
        sX[k * 129 + nl] = X[(kc * 32 + k) * NB + nt * 128 + nl];
    }
    __syncthreads();
    uint32_t* dst = out + (nt * 16 + kc) * 2048;
#pragma unroll
    for (int i = 0; i < 8; i++) {
        int w = t + i * 256;                   // 0..2047
        int n_loc = w >> 4, kp = w & 15;
        int k0 = kp * 2;
        dst[w] = pack_bf(sX[k0 * 129 + n_loc], sX[(k0 + 1) * 129 + n_loc]);
    }
}

// ---------------------------------------------------------------------------
// v3[a,n] = sum_d core3[a,d] * X2[d,n].  grid 256 CTAs (16 cols each), 256 thr.
// ---------------------------------------------------------------------------
__global__ __launch_bounds__(256)
void v3_kernel(const float* __restrict__ core3, const float* __restrict__ X2)
{
    __shared__ float Xs[64][17];
    const int t = threadIdx.x, n0 = blockIdx.x * 16;
    const int a = t >> 3, ncp = (t & 7) * 2;
    float acc0 = 0.f, acc1 = 0.f;
    for (int d0 = 0; d0 < D; d0 += 64) {
#pragma unroll
        for (int i = 0; i < 4; i++) {
            int idx = t + i * 256;
            Xs[idx >> 4][idx & 15] = X2[(d0 + (idx >> 4)) * NB + n0 + (idx & 15)];
        }
        __syncthreads();
#pragma unroll
        for (int dl = 0; dl < 64; dl++) {
            float cv = core3[a * D + d0 + dl];
            acc0 += cv * Xs[dl][ncp];
            acc1 += cv * Xs[dl][ncp + 1];
        }
        __syncthreads();
    }
    g_V3[a * NB + n0 + ncp]     = acc0;
    g_V3[a * NB + n0 + ncp + 1] = acc1;
}

// ---------------------------------------------------------------------------
// Tensor GEMM 128m x 256n, 512 threads / 16 warps (4 per SMSP).  [R12 verbatim]
// warps: wm = warp&3 (32 m rows = one 'a'), wn = warp>>2 (64-col n slice).
// grid (nq=16, mt=8) = 128 CTAs. BK=32, 3-stage cp.async, 80B-padded rows.
// pass 0: A=g_A2, B=g_B1, scale=g_V3, out=g_u2
// pass 1: A=g_A1, B=g_B0, scale=g_u2, out=g_u1
// out[a, n] = (1/64) * sum_b C[a*32+b, n] * scale[b, n],  a = mt*4 + wm.
// ---------------------------------------------------------------------------
__global__ __launch_bounds__(512, 1)
void tt_gemm_kernel(int pass)
{
    const uint32_t* __restrict__ Apk   = (pass == 0) ? g_A2 : g_A1;
    const uint32_t* __restrict__ Bpk   = (pass == 0) ? g_B1 : g_B0;
    const float*    __restrict__ scale = (pass == 0) ? g_V3 : g_u2;
    float*          __restrict__ out   = (pass == 0) ? g_u2 : g_u1;

    extern __shared__ char smem[];
    const int t = threadIdx.x, warp = t >> 5, lane = t & 31;
    const int wm = warp & 3, wn = warp >> 2;        // wn 0..3: 64-col slice
    const int g = lane >> 2, c = lane & 3;
    const int nq = blockIdx.x, mt = blockIdx.y;
    const uint32_t sbase = smem_u32(smem);

    const int mat  = lane >> 3;          // 0..3
    const int mrow = lane & 7;
    const int hA = mat >> 1;                                     // A k-half
    const int rA0 = (wm * 2 + 0) * 16 + (mat & 1) * 8 + mrow;    // i=0 row
    const int rA1 = rA0 + 16;                                    // i=1 row
    const int hB = mat & 1;                                      // B k-half
    const int rB = (wn & 1) * 64 + (mat >> 1) * 8 + mrow;        // + jp*8

    // scale tile: 32 x 256, stride 260
    float* sS = (float*)smem;
#pragma unroll
    for (int i = 0; i < 16; i++) {
        int idx = t + i * 512;
        sS[(idx >> 8) * 260 + (idx & 255)] = scale[(idx >> 8) * NB + nq * 256 + (idx & 255)];
    }

    const uint32_t* Asrc  = Apk + mt * 32768;             // 16 kc * 2048
    const uint32_t* B0src = Bpk + (nq * 2 + 0) * 32768;
    const uint32_t* B1src = Bpk + (nq * 2 + 1) * 32768;

    float acc[2][8][4];
#pragma unroll
    for (int i = 0; i < 2; i++)
#pragma unroll
        for (int j = 0; j < 8; j++)
#pragma unroll
            for (int q = 0; q < 4; q++) acc[i][j][q] = 0.f;

    // padded smem offset for this thread's 16B chunk
    const uint32_t o1 = (uint32_t)t * 16 + (uint32_t)(t & ~3) * 4;

    auto issue = [&](int kc) {
        uint32_t sd = sbase + SM_ST + (kc % 3) * STAGE_B;
        cp16(sd + o1,              (const uint4*)(Asrc  + kc * 2048) + t);
        cp16(sd + TILE_B + o1,     (const uint4*)(B0src + kc * 2048) + t);
        cp16(sd + 2 * TILE_B + o1, (const uint4*)(B1src + kc * 2048) + t);
        CP_COMMIT();
    };
    issue(0);
    issue(1);

    for (int kc = 0; kc < 16; kc++) {
        if (kc < 15)
            asm volatile("cp.async.wait_group 1;" ::: "memory");
        else
            asm volatile("cp.async.wait_group 0;" ::: "memory");
        __syncthreads();                       // stage kc visible to all
        if (kc + 2 < 16) issue(kc + 2);        // overwrites stage (kc-1)%3: safe

        const uint32_t sA = sbase + SM_ST + (kc % 3) * STAGE_B;
        const uint32_t sB = sA + TILE_B + (uint32_t)(wn >> 1) * TILE_B;

#pragma unroll
        for (int ks = 0; ks < 2; ks++) {
            uint32_t ah[2][4];
            {
                uint32_t kgA = (uint32_t)(ks * 2 + hA);
                ldsm4(ah[0], sA + (uint32_t)rA0 * 80 + kgA * 16);
                ldsm4(ah[1], sA + (uint32_t)rA1 * 80 + kgA * 16);
            }
#pragma unroll
            for (int jp = 0; jp < 8; jp += 2) {
                uint32_t bb[4];
                {
                    int rn = rB + jp * 8;
                    uint32_t kgB = (uint32_t)(ks * 2 + hB);
                    ldsm4(bb, sB + (uint32_t)rn * 80 + kgB * 16);
                }
#pragma unroll
                for (int i = 0; i < 2; i++) {
                    mma16816(acc[i][jp],     ah[i], bb);
                    mma16816(acc[i][jp + 1], ah[i], bb + 2);
                }
            }
        }
    }

    // epilogue: contract over b = rows of the warp's 32-row strip, unscale
    const int a = mt * 4 + wm;
    float* dst = out + a * NB + nq * 256 + wn * 64;
#pragma unroll
    for (int j = 0; j < 8; j++) {
        int col0 = wn * 64 + j * 8 + c * 2;
        float p0 = 0.f, p1 = 0.f;
#pragma unroll
        for (int i = 0; i < 2; i++) {
            int b0 = i * 16 + g, b1 = b0 + 8;
            p0 += acc[i][j][0] * sS[b0 * 260 + col0] + acc[i][j][2] * sS[b1 * 260 + col0];
            p1 += acc[i][j][1] * sS[b0 * 260 + col0 + 1] + acc[i][j][3] * sS[b1 * 260 + col0 + 1];
        }
#pragma unroll
        for (int off = 4; off <= 16; off <<= 1) {
            p0 += __shfl_xor_sync(0xffffffffu, p0, off);
            p1 += __shfl_xor_sync(0xffffffffu, p1, off);
        }
        if (g == 0)
            *(float2*)&dst[j * 8 + c * 2] = make_float2(p0 * UNSCALE, p1 * UNSCALE);
    }
}

// ---------------------------------------------------------------------------
// Z[o,n] = sum_a core0[o*32+a] * u1[a,n].  grid (32 nt, 8 og) = 256 CTAs,
// 256 thr, 64 o x 128 n per CTA.  cs read as float4 (4 'a' per LDS.128,
// broadcast across warp) + 2-way output ILP -> FFMA-bound.
// ---------------------------------------------------------------------------
__global__ __launch_bounds__(256)
void z_kernel(const float* __restrict__ core0, float* __restrict__ Z)
{
    __shared__ float cs[64 * 32];      // [o_loc][a], 8 KB
    __shared__ float u1s[32][133];
    const int t = threadIdx.x, nt = blockIdx.x, og = blockIdx.y;
    const int n0 = nt * 128;
#pragma unroll
    for (int i = 0; i < 8; i++)
        cs[i * 256 + t] = core0[og * 64 * 32 + i * 256 + t];
#pragma unroll
    for (int i = 0; i < 16; i++) {
        int idx = t + i * 256;
        u1s[idx >> 7][idx & 127] = g_u1[(idx >> 7) * NB + n0 + (idx & 127)];
    }
    __syncthreads();
    const int j = t & 127, to = t >> 7;            // to: 0..1 -> 32 o each
    float u1r[32];
#pragma unroll
    for (int a = 0; a < 32; a++) u1r[a] = u1s[a][j];

    const float4* cs4 = (const float4*)cs;
#pragma unroll
    for (int oo = 0; oo < 32; oo += 2) {
        int ol0 = to * 32 + oo;
        float p0 = 0.f, p1 = 0.f;
#pragma unroll
        for (int q = 0; q < 8; q++) {
            float4 c0 = cs4[ol0 * 8 + q];          // broadcast LDS.128
            float4 c1 = cs4[(ol0 + 1) * 8 + q];
            p0 += c0.x * u1r[q * 4]     + c0.y * u1r[q * 4 + 1]
                + c0.z * u1r[q * 4 + 2] + c0.w * u1r[q * 4 + 3];
            p1 += c1.x * u1r[q * 4]     + c1.y * u1r[q * 4 + 1]
                + c1.z * u1r[q * 4 + 2] + c1.w * u1r[q * 4 + 3];
        }
        Z[(og * 64 + ol0) * NB + n0 + j]     = p0;
        Z[(og * 64 + ol0 + 1) * NB + n0 + j] = p1;
    }
}

// ---------------------------------------------------------------------------
extern "C" void kernel_launch(void* const* d_in, const int* in_sizes, int n_in,
                              void* d_out, int out_size)
{
    const float* X0    = (const float*)d_in[0];
    const float* X1    = (const float*)d_in[1];
    const float* X2    = (const float*)d_in[2];
    const float* core0 = (const float*)d_in[3];
    const float* core1 = (const float*)d_in[4];
    const float* core2 = (const float*)d_in[5];
    const float* core3 = (const float*)d_in[6];
    float* Z = (float*)d_out;

    static bool attr_done = false;
    if (!attr_done) {
        cudaFuncSetAttribute(tt_gemm_kernel,
                             cudaFuncAttributeMaxDynamicSharedMemorySize, SM_TOTAL);
        attr_done = true;
    }

    pack_core_kernel<<<dim3(8, 16, 2), 256>>>(core1, core2);
    pack_x_kernel<<<dim3(32, 16, 2), 256>>>(X0, X1);
    v3_kernel<<<256, 256>>>(core3, X2);
    tt_gemm_kernel<<<dim3(16, 8), 512, SM_TOTAL>>>(0);  // core2 x X1, scale v3 -> u2
    tt_gemm_kernel<<<dim3(16, 8), 512, SM_TOTAL>>>(1);  // core1 x X0, scale u2 -> u1
    z_kernel<<<dim3(32, 8), 256>>>(core0, Z);
}